// round 2
// baseline (speedup 1.0000x reference)
#include <cuda_runtime.h>

#define Hd 128
#define MAXM 50048
#define MAXL 400128
#define SEPS 1e-9f

// ---------------- scratch (device globals; no allocations) ----------------
__device__ float g_Bx [MAXM*Hd];
__device__ float g_Wix[MAXM*Hd];
__device__ float g_Wfx[MAXM*Hd];
__device__ float g_Wox[MAXM*Hd];
__device__ float g_Wcx[MAXM*Hd];
__device__ float g_Ah [MAXM*Hd];
__device__ float g_Ufh[MAXM*Hd];
__device__ float g_hhat[MAXM*Hd];
__device__ float g_sumfc[MAXM*Hd];
__device__ float g_Uih[MAXM*Hd];
__device__ float g_Uch[MAXM*Hd];
__device__ float g_Uoh[MAXM*Hd];
__device__ float g_e[MAXL];
__device__ float g_segsum[MAXM];
__device__ unsigned g_segmax[MAXM];

// ---------------- helpers ----------------
__device__ __forceinline__ float sigm_f(float x) {
    // 1/(1+exp(-x)) via MUFU.EX2 + approx divide (~2 ulp)
    return __fdividef(1.0f, 1.0f + __expf(-x));
}
__device__ __forceinline__ float tanh_f(float x) {
    // tanh(x) = 1 - 2/(exp(2x)+1); exp overflow -> inf -> 2/inf=0 -> 1 (correct)
    float e2 = __expf(2.0f * x);
    return 1.0f - __fdividef(2.0f, e2 + 1.0f);
}
// monotonic unsigned encoding of float for atomicMax; enc of any finite float > 0,
// so zero-init is a valid "-inf" sentinel.
__device__ __forceinline__ unsigned encf(float f) {
    unsigned b = __float_as_uint(f);
    return (b & 0x80000000u) ? ~b : (b | 0x80000000u);
}
__device__ __forceinline__ float decf(unsigned u) {
    return (u & 0x80000000u) ? __uint_as_float(u ^ 0x80000000u) : __uint_as_float(~u);
}
__device__ __forceinline__ void red4(float* p, float x, float y, float z, float w) {
    asm volatile("red.global.add.v4.f32 [%0], {%1, %2, %3, %4};"
                 :: "l"(p), "f"(x), "f"(y), "f"(z), "f"(w) : "memory");
}

// ---------------- zero scratch accumulators ----------------
__global__ void zero_kernel(int M) {
    int n4 = M * Hd / 4;
    float4 z = make_float4(0.f, 0.f, 0.f, 0.f);
    int stride = gridDim.x * blockDim.x;
    for (int i = blockIdx.x * blockDim.x + threadIdx.x; i < n4; i += stride) {
        ((float4*)g_hhat)[i]  = z;
        ((float4*)g_sumfc)[i] = z;
    }
    for (int i = blockIdx.x * blockDim.x + threadIdx.x; i < M; i += stride) {
        g_segsum[i] = 0.f;
        g_segmax[i] = 0u;
    }
}

// ---------------- batched 128xK GEMM: C = A @ W^T (+bias) ----------------
// A: [M,128] row-major, W: [128,128] row-major (C[m][n] = sum_k A[m][k]*W[n][k])
struct GemmArgs {
    const float* A;
    const float* W[5];
    const float* bias[5];
    float* C[5];
    int M;
};

__global__ void __launch_bounds__(256, 2) gemm128(GemmArgs ga) {
    const float* __restrict__ A    = ga.A;
    const float* __restrict__ W    = ga.W[blockIdx.y];
    const float* __restrict__ bias = ga.bias[blockIdx.y];
    float* __restrict__ C          = ga.C[blockIdx.y];
    const int M = ga.M;

    __shared__ float As[32][Hd];
    __shared__ float Ws[32][Hd];

    const int tid  = threadIdx.x;
    const int lrow = tid & 127;   // load row (m within tile / n for W)
    const int lc   = tid >> 7;    // 0/1: which half of the k-slice columns
    const int m0   = blockIdx.x * 128;
    const int tn   = (tid & 15) * 8;
    const int tm   = (tid >> 4) * 8;

    float acc[8][8];
#pragma unroll
    for (int i = 0; i < 8; i++)
#pragma unroll
        for (int j = 0; j < 8; j++) acc[i][j] = 0.f;

    const bool arow_ok = (m0 + lrow) < M;
    const float4* Arow = (const float4*)(A + (size_t)(m0 + lrow) * Hd);
    const float4* Wrow = (const float4*)(W + (size_t)lrow * Hd);

    for (int k0 = 0; k0 < Hd; k0 += 32) {
#pragma unroll
        for (int i = 0; i < 4; i++) {
            int kk = lc * 4 + i * 8;          // 0..31 (mult of 4)
            float4 av = arow_ok ? Arow[(k0 + kk) >> 2] : make_float4(0.f, 0.f, 0.f, 0.f);
            As[kk + 0][lrow] = av.x;
            As[kk + 1][lrow] = av.y;
            As[kk + 2][lrow] = av.z;
            As[kk + 3][lrow] = av.w;
            float4 wv = Wrow[(k0 + kk) >> 2];
            Ws[kk + 0][lrow] = wv.x;
            Ws[kk + 1][lrow] = wv.y;
            Ws[kk + 2][lrow] = wv.z;
            Ws[kk + 3][lrow] = wv.w;
        }
        __syncthreads();
#pragma unroll
        for (int kk = 0; kk < 32; kk++) {
            float a[8], b[8];
            *(float4*)&a[0] = *(const float4*)&As[kk][tm];
            *(float4*)&a[4] = *(const float4*)&As[kk][tm + 4];
            *(float4*)&b[0] = *(const float4*)&Ws[kk][tn];
            *(float4*)&b[4] = *(const float4*)&Ws[kk][tn + 4];
#pragma unroll
            for (int i = 0; i < 8; i++)
#pragma unroll
                for (int j = 0; j < 8; j++)
                    acc[i][j] = fmaf(a[i], b[j], acc[i][j]);
        }
        __syncthreads();
    }

    float bv[8];
    if (bias) {
        *(float4*)&bv[0] = *(const float4*)(bias + tn);
        *(float4*)&bv[4] = *(const float4*)(bias + tn + 4);
    } else {
#pragma unroll
        for (int j = 0; j < 8; j++) bv[j] = 0.f;
    }
#pragma unroll
    for (int i = 0; i < 8; i++) {
        int m = m0 + tm + i;
        if (m < M) {
            float4 o0 = make_float4(acc[i][0] + bv[0], acc[i][1] + bv[1],
                                    acc[i][2] + bv[2], acc[i][3] + bv[3]);
            float4 o1 = make_float4(acc[i][4] + bv[4], acc[i][5] + bv[5],
                                    acc[i][6] + bv[6], acc[i][7] + bv[7]);
            *(float4*)(C + (size_t)m * Hd + tn)     = o0;
            *(float4*)(C + (size_t)m * Hd + tn + 4) = o1;
        }
    }
}

// ---------------- pair pass 1: e = tanh(Ah[chi]+Bx[ci]) . v ; segmax ----------------
__global__ void pair_e_kernel(const int* __restrict__ ci, const int* __restrict__ chi,
                              const float* __restrict__ v, int L) {
    __shared__ float vs[Hd];
    if (threadIdx.x < Hd) vs[threadIdx.x] = v[threadIdx.x];
    __syncthreads();

    int w = blockIdx.x * (blockDim.x >> 5) + (threadIdx.x >> 5);
    int lane = threadIdx.x & 31;
    if (w >= L) return;

    int c  = __ldg(ci + w);
    int ch = __ldg(chi + w);
    float4 a  = *(const float4*)(g_Ah + (size_t)ch * Hd + lane * 4);
    float4 b  = *(const float4*)(g_Bx + (size_t)c * Hd + lane * 4);
    float4 vv = *(const float4*)(vs + lane * 4);

    float s = tanh_f(a.x + b.x) * vv.x + tanh_f(a.y + b.y) * vv.y +
              tanh_f(a.z + b.z) * vv.z + tanh_f(a.w + b.w) * vv.w;
#pragma unroll
    for (int o = 16; o; o >>= 1) s += __shfl_xor_sync(0xFFFFFFFFu, s, o);

    if (lane == 0) {
        g_e[w] = s;
        atomicMax(g_segmax + c, encf(s));
    }
}

// ---------------- pair pass 2: xexp = exp(e - segmax[ci]); segsum ----------------
__global__ void pair_exp_kernel(const int* __restrict__ ci, int L) {
    int l = blockIdx.x * blockDim.x + threadIdx.x;
    if (l >= L) return;
    int c = ci[l];
    float mx = decf(g_segmax[c]);
    float xe = __expf(g_e[l] - mx);
    g_e[l] = xe;
    atomicAdd(g_segsum + c, xe);
}

// ---------------- pair pass 3: h_hat and sum_f_c accumulation ----------------
__global__ void pair_acc_kernel(const float* __restrict__ child_h,
                                const float* __restrict__ child_c,
                                const int* __restrict__ ci, const int* __restrict__ chi,
                                int L) {
    int w = blockIdx.x * (blockDim.x >> 5) + (threadIdx.x >> 5);
    int lane = threadIdx.x & 31;
    if (w >= L) return;

    int c  = __ldg(ci + w);
    int ch = __ldg(chi + w);
    float attn = __ldg(g_e + w) / (__ldg(g_segsum + c) + SEPS);

    size_t co  = (size_t)c * Hd + lane * 4;
    size_t cho = (size_t)ch * Hd + lane * 4;

    float4 hv = *(const float4*)(child_h + cho);
    red4(g_hhat + co, attn * hv.x, attn * hv.y, attn * hv.z, attn * hv.w);

    float4 wf = *(const float4*)(g_Wfx + co);
    float4 uf = *(const float4*)(g_Ufh + cho);
    float4 cv = *(const float4*)(child_c + cho);
    float fx = sigm_f(wf.x + uf.x) * cv.x;
    float fy = sigm_f(wf.y + uf.y) * cv.y;
    float fz = sigm_f(wf.z + uf.z) * cv.z;
    float fw = sigm_f(wf.w + uf.w) * cv.w;
    red4(g_sumfc + co, fx, fy, fz, fw);
}

// ---------------- epilogue: gates -> h, c ----------------
__global__ void epilogue_kernel(float* __restrict__ outh, float* __restrict__ outc, int n4) {
    int stride = gridDim.x * blockDim.x;
    for (int i = blockIdx.x * blockDim.x + threadIdx.x; i < n4; i += stride) {
        float4 wix = ((const float4*)g_Wix)[i];
        float4 uih = ((const float4*)g_Uih)[i];
        float4 wcx = ((const float4*)g_Wcx)[i];
        float4 uch = ((const float4*)g_Uch)[i];
        float4 wox = ((const float4*)g_Wox)[i];
        float4 uoh = ((const float4*)g_Uoh)[i];
        float4 sf  = ((const float4*)g_sumfc)[i];

        float4 hc, cc;
        {
            float ig = sigm_f(wix.x + uih.x);
            float ct = tanh_f(wcx.x + uch.x);
            float cval = fmaf(ig, ct, sf.x);
            float og = sigm_f(wox.x + uoh.x);
            cc.x = cval; hc.x = og * tanh_f(cval);
        }
        {
            float ig = sigm_f(wix.y + uih.y);
            float ct = tanh_f(wcx.y + uch.y);
            float cval = fmaf(ig, ct, sf.y);
            float og = sigm_f(wox.y + uoh.y);
            cc.y = cval; hc.y = og * tanh_f(cval);
        }
        {
            float ig = sigm_f(wix.z + uih.z);
            float ct = tanh_f(wcx.z + uch.z);
            float cval = fmaf(ig, ct, sf.z);
            float og = sigm_f(wox.z + uoh.z);
            cc.z = cval; hc.z = og * tanh_f(cval);
        }
        {
            float ig = sigm_f(wix.w + uih.w);
            float ct = tanh_f(wcx.w + uch.w);
            float cval = fmaf(ig, ct, sf.w);
            float og = sigm_f(wox.w + uoh.w);
            cc.w = cval; hc.w = og * tanh_f(cval);
        }
        ((float4*)outh)[i] = hc;
        ((float4*)outc)[i] = cc;
    }
}

// ---------------- launch ----------------
extern "C" void kernel_launch(void* const* d_in, const int* in_sizes, int n_in,
                              void* d_out, int out_size) {
    const float* x_emb   = (const float*)d_in[0];
    const float* child_h = (const float*)d_in[1];
    const float* child_c = (const float*)d_in[2];
    const int*   ci      = (const int*)d_in[3];
    const int*   chi     = (const int*)d_in[4];
    const float* Wi_w = (const float*)d_in[5];
    const float* Ui_w = (const float*)d_in[6];
    const float* Wf_w = (const float*)d_in[7];
    const float* Uf_w = (const float*)d_in[8];
    const float* Wo_w = (const float*)d_in[9];
    const float* Uo_w = (const float*)d_in[10];
    const float* Wc_w = (const float*)d_in[11];
    const float* Uc_w = (const float*)d_in[12];
    const float* Wa_w = (const float*)d_in[13];
    const float* Ua_w = (const float*)d_in[14];
    const float* Wi_b = (const float*)d_in[15];
    const float* Wf_b = (const float*)d_in[16];
    const float* Wo_b = (const float*)d_in[17];
    const float* Wc_b = (const float*)d_in[18];
    const float* Wa_b = (const float*)d_in[19];
    const float* v_w  = (const float*)d_in[20];

    const int M = in_sizes[0] / Hd;
    const int L = in_sizes[3];

    float *p_Bx, *p_Wix, *p_Wfx, *p_Wox, *p_Wcx, *p_Ah, *p_Ufh, *p_hhat, *p_Uih, *p_Uch, *p_Uoh;
    cudaGetSymbolAddress((void**)&p_Bx,  g_Bx);
    cudaGetSymbolAddress((void**)&p_Wix, g_Wix);
    cudaGetSymbolAddress((void**)&p_Wfx, g_Wfx);
    cudaGetSymbolAddress((void**)&p_Wox, g_Wox);
    cudaGetSymbolAddress((void**)&p_Wcx, g_Wcx);
    cudaGetSymbolAddress((void**)&p_Ah,  g_Ah);
    cudaGetSymbolAddress((void**)&p_Ufh, g_Ufh);
    cudaGetSymbolAddress((void**)&p_hhat, g_hhat);
    cudaGetSymbolAddress((void**)&p_Uih, g_Uih);
    cudaGetSymbolAddress((void**)&p_Uch, g_Uch);
    cudaGetSymbolAddress((void**)&p_Uoh, g_Uoh);

    float* outh = (float*)d_out;
    float* outc = outh + (size_t)M * Hd;

    const int mtiles = (M + 127) / 128;

    zero_kernel<<<296, 256>>>(M);

    // x-side GEMMs: Bx, Wix, Wfx, Wox, Wcx
    {
        GemmArgs ga;
        ga.A = x_emb; ga.M = M;
        ga.W[0] = Ua_w; ga.bias[0] = nullptr; ga.C[0] = p_Bx;
        ga.W[1] = Wi_w; ga.bias[1] = Wi_b;    ga.C[1] = p_Wix;
        ga.W[2] = Wf_w; ga.bias[2] = Wf_b;    ga.C[2] = p_Wfx;
        ga.W[3] = Wo_w; ga.bias[3] = Wo_b;    ga.C[3] = p_Wox;
        ga.W[4] = Wc_w; ga.bias[4] = Wc_b;    ga.C[4] = p_Wcx;
        gemm128<<<dim3(mtiles, 5), 256>>>(ga);
    }
    // child_h-side GEMMs: Ah (+Wa_b), Ufh
    {
        GemmArgs ga;
        ga.A = child_h; ga.M = M;
        ga.W[0] = Wa_w; ga.bias[0] = Wa_b;    ga.C[0] = p_Ah;
        ga.W[1] = Uf_w; ga.bias[1] = nullptr; ga.C[1] = p_Ufh;
        ga.W[2] = ga.W[1]; ga.bias[2] = nullptr; ga.C[2] = p_Ufh;  // unused slots
        ga.W[3] = ga.W[1]; ga.bias[3] = nullptr; ga.C[3] = p_Ufh;
        ga.W[4] = ga.W[1]; ga.bias[4] = nullptr; ga.C[4] = p_Ufh;
        gemm128<<<dim3(mtiles, 2), 256>>>(ga);
    }

    // attention + forget-gate pair passes
    pair_e_kernel<<<(L + 7) / 8, 256>>>(ci, chi, v_w, L);
    pair_exp_kernel<<<(L + 255) / 256, 256>>>(ci, L);
    pair_acc_kernel<<<(L + 7) / 8, 256>>>(child_h, child_c, ci, chi, L);

    // h_hat-side GEMMs: Uih, Uch, Uoh
    {
        GemmArgs ga;
        ga.A = p_hhat; ga.M = M;
        ga.W[0] = Ui_w; ga.bias[0] = nullptr; ga.C[0] = p_Uih;
        ga.W[1] = Uc_w; ga.bias[1] = nullptr; ga.C[1] = p_Uch;
        ga.W[2] = Uo_w; ga.bias[2] = nullptr; ga.C[2] = p_Uoh;
        ga.W[3] = ga.W[0]; ga.bias[3] = nullptr; ga.C[3] = p_Uih;  // unused
        ga.W[4] = ga.W[0]; ga.bias[4] = nullptr; ga.C[4] = p_Uih;
        gemm128<<<dim3(mtiles, 3), 256>>>(ga);
    }

    const int n4 = M * Hd / 4;
    epilogue_kernel<<<(n4 + 255) / 256, 256>>>(outh, outc, n4);
}

// round 3
// speedup vs baseline: 1.0301x; 1.0301x over previous
#include <cuda_runtime.h>

#define Hd 128
#define MAXM 50048
#define MAXL 400128
#define SEPS 1e-9f

// ---------------- scratch (device globals; no allocations) ----------------
__device__ float g_Bx [MAXM*Hd];
__device__ float g_Wix[MAXM*Hd];
__device__ float g_Wfx[MAXM*Hd];
__device__ float g_Wox[MAXM*Hd];
__device__ float g_Wcx[MAXM*Hd];
__device__ float g_Ah [MAXM*Hd];
__device__ float g_Ufh[MAXM*Hd];
__device__ float g_hhat[MAXM*Hd];
__device__ float g_sumfc[MAXM*Hd];
__device__ float g_Uih[MAXM*Hd];
__device__ float g_Uch[MAXM*Hd];
__device__ float g_Uoh[MAXM*Hd];
__device__ float g_e[MAXL];
__device__ float g_segsum[MAXM];
__device__ unsigned g_segmax[MAXM];

// ---------------- helpers ----------------
__device__ __forceinline__ float sigm_f(float x) {
    return __fdividef(1.0f, 1.0f + __expf(-x));
}
__device__ __forceinline__ float tanh_f(float x) {
    float e2 = __expf(2.0f * x);
    return 1.0f - __fdividef(2.0f, e2 + 1.0f);
}
__device__ __forceinline__ unsigned encf(float f) {
    unsigned b = __float_as_uint(f);
    return (b & 0x80000000u) ? ~b : (b | 0x80000000u);
}
__device__ __forceinline__ float decf(unsigned u) {
    return (u & 0x80000000u) ? __uint_as_float(u ^ 0x80000000u) : __uint_as_float(~u);
}
__device__ __forceinline__ void red4(float* p, float x, float y, float z, float w) {
    asm volatile("red.global.add.v4.f32 [%0], {%1, %2, %3, %4};"
                 :: "l"(p), "f"(x), "f"(y), "f"(z), "f"(w) : "memory");
}

// packed f32x2 (FFMA2) helpers — only reachable via PTX
__device__ __forceinline__ unsigned long long pack_dup(float x) {
    unsigned long long r;
    asm("mov.b64 %0, {%1, %1};" : "=l"(r) : "f"(x));
    return r;
}
__device__ __forceinline__ void unpack2(unsigned long long v, float& lo, float& hi) {
    asm("mov.b64 {%0, %1}, %2;" : "=f"(lo), "=f"(hi) : "l"(v));
}
__device__ __forceinline__ unsigned long long fma2(unsigned long long a,
                                                   unsigned long long b,
                                                   unsigned long long c) {
    unsigned long long d;
    asm("fma.rn.f32x2 %0, %1, %2, %3;" : "=l"(d) : "l"(a), "l"(b), "l"(c));
    return d;
}

// ---------------- zero scratch accumulators ----------------
__global__ void zero_kernel(int M) {
    int n4 = M * Hd / 4;
    float4 z = make_float4(0.f, 0.f, 0.f, 0.f);
    int stride = gridDim.x * blockDim.x;
    for (int i = blockIdx.x * blockDim.x + threadIdx.x; i < n4; i += stride) {
        ((float4*)g_hhat)[i]  = z;
        ((float4*)g_sumfc)[i] = z;
    }
    for (int i = blockIdx.x * blockDim.x + threadIdx.x; i < M; i += stride) {
        g_segsum[i] = 0.f;
        g_segmax[i] = 0u;
    }
}

// ---------------- batched 128xK GEMM: C = A @ W^T (+bias), FFMA2 core ----------------
// A: [M,128] row-major, W: [128,128] row-major (C[m][n] = sum_k A[m][k]*W[n][k])
struct GemmArgs {
    const float* A[7];
    const float* W[7];
    const float* bias[7];
    float* C[7];
    int M;
};

__global__ void __launch_bounds__(256, 2) gemm128(GemmArgs ga) {
    const float* __restrict__ A    = ga.A[blockIdx.y];
    const float* __restrict__ W    = ga.W[blockIdx.y];
    const float* __restrict__ bias = ga.bias[blockIdx.y];
    float* __restrict__ C          = ga.C[blockIdx.y];
    const int M = ga.M;

    __shared__ float As[32][Hd];
    __shared__ float Ws[32][Hd];

    const int tid  = threadIdx.x;
    const int lrow = tid & 127;   // load row (m within tile / n for W)
    const int lc   = tid >> 7;    // 0/1: which half of the k-slice columns
    const int m0   = blockIdx.x * 128;
    const int tn   = (tid & 15) * 8;
    const int tm   = (tid >> 4) * 8;

    // acc2[i][j]: packed (c[i][2j], c[i][2j+1])
    unsigned long long acc2[8][4];
#pragma unroll
    for (int i = 0; i < 8; i++)
#pragma unroll
        for (int j = 0; j < 4; j++) acc2[i][j] = 0ull;

    const bool arow_ok = (m0 + lrow) < M;
    const float4* Arow = (const float4*)(A + (size_t)(m0 + lrow) * Hd);
    const float4* Wrow = (const float4*)(W + (size_t)lrow * Hd);

    for (int k0 = 0; k0 < Hd; k0 += 32) {
#pragma unroll
        for (int i = 0; i < 4; i++) {
            int kk = lc * 4 + i * 8;          // 0..31 (mult of 4)
            float4 av = arow_ok ? Arow[(k0 + kk) >> 2] : make_float4(0.f, 0.f, 0.f, 0.f);
            As[kk + 0][lrow] = av.x;
            As[kk + 1][lrow] = av.y;
            As[kk + 2][lrow] = av.z;
            As[kk + 3][lrow] = av.w;
            float4 wv = Wrow[(k0 + kk) >> 2];
            Ws[kk + 0][lrow] = wv.x;
            Ws[kk + 1][lrow] = wv.y;
            Ws[kk + 2][lrow] = wv.z;
            Ws[kk + 3][lrow] = wv.w;
        }
        __syncthreads();
#pragma unroll
        for (int kk = 0; kk < 32; kk++) {
            float a[8];
            *(float4*)&a[0] = *(const float4*)&As[kk][tm];
            *(float4*)&a[4] = *(const float4*)&As[kk][tm + 4];
            // B pairs load straight from shared as 64-bit lanes (no pack cost)
            ulonglong2 b01 = *(const ulonglong2*)&Ws[kk][tn];
            ulonglong2 b23 = *(const ulonglong2*)&Ws[kk][tn + 4];
#pragma unroll
            for (int i = 0; i < 8; i++) {
                unsigned long long a2 = pack_dup(a[i]);
                acc2[i][0] = fma2(a2, b01.x, acc2[i][0]);
                acc2[i][1] = fma2(a2, b01.y, acc2[i][1]);
                acc2[i][2] = fma2(a2, b23.x, acc2[i][2]);
                acc2[i][3] = fma2(a2, b23.y, acc2[i][3]);
            }
        }
        __syncthreads();
    }

    float bv[8];
    if (bias) {
        *(float4*)&bv[0] = *(const float4*)(bias + tn);
        *(float4*)&bv[4] = *(const float4*)(bias + tn + 4);
    } else {
#pragma unroll
        for (int j = 0; j < 8; j++) bv[j] = 0.f;
    }
#pragma unroll
    for (int i = 0; i < 8; i++) {
        int m = m0 + tm + i;
        if (m < M) {
            float c[8];
#pragma unroll
            for (int j = 0; j < 4; j++) unpack2(acc2[i][j], c[2 * j], c[2 * j + 1]);
            float4 o0 = make_float4(c[0] + bv[0], c[1] + bv[1], c[2] + bv[2], c[3] + bv[3]);
            float4 o1 = make_float4(c[4] + bv[4], c[5] + bv[5], c[6] + bv[6], c[7] + bv[7]);
            *(float4*)(C + (size_t)m * Hd + tn)     = o0;
            *(float4*)(C + (size_t)m * Hd + tn + 4) = o1;
        }
    }
}

// ---------------- pair pass 1: e = tanh(Ah[chi]+Bx[ci]) . v ; segmax ----------------
__global__ void pair_e_kernel(const int* __restrict__ ci, const int* __restrict__ chi,
                              const float* __restrict__ v, int L) {
    __shared__ float vs[Hd];
    if (threadIdx.x < Hd) vs[threadIdx.x] = v[threadIdx.x];
    __syncthreads();

    int w = blockIdx.x * (blockDim.x >> 5) + (threadIdx.x >> 5);
    int lane = threadIdx.x & 31;
    if (w >= L) return;

    int c  = __ldg(ci + w);
    int ch = __ldg(chi + w);
    float4 a  = *(const float4*)(g_Ah + (size_t)ch * Hd + lane * 4);
    float4 b  = *(const float4*)(g_Bx + (size_t)c * Hd + lane * 4);
    float4 vv = *(const float4*)(vs + lane * 4);

    float s = tanh_f(a.x + b.x) * vv.x + tanh_f(a.y + b.y) * vv.y +
              tanh_f(a.z + b.z) * vv.z + tanh_f(a.w + b.w) * vv.w;
#pragma unroll
    for (int o = 16; o; o >>= 1) s += __shfl_xor_sync(0xFFFFFFFFu, s, o);

    if (lane == 0) {
        g_e[w] = s;
        atomicMax(g_segmax + c, encf(s));
    }
}

// ---------------- pair pass 2: xexp = exp(e - segmax[ci]); segsum ----------------
__global__ void pair_exp_kernel(const int* __restrict__ ci, int L) {
    int l = blockIdx.x * blockDim.x + threadIdx.x;
    if (l >= L) return;
    int c = ci[l];
    float mx = decf(g_segmax[c]);
    float xe = __expf(g_e[l] - mx);
    g_e[l] = xe;
    atomicAdd(g_segsum + c, xe);
}

// ---------------- pair pass 3: h_hat and sum_f_c accumulation ----------------
__global__ void pair_acc_kernel(const float* __restrict__ child_h,
                                const float* __restrict__ child_c,
                                const int* __restrict__ ci, const int* __restrict__ chi,
                                int L) {
    int w = blockIdx.x * (blockDim.x >> 5) + (threadIdx.x >> 5);
    int lane = threadIdx.x & 31;
    if (w >= L) return;

    int c  = __ldg(ci + w);
    int ch = __ldg(chi + w);
    float attn = __ldg(g_e + w) / (__ldg(g_segsum + c) + SEPS);

    size_t co  = (size_t)c * Hd + lane * 4;
    size_t cho = (size_t)ch * Hd + lane * 4;

    float4 hv = *(const float4*)(child_h + cho);
    red4(g_hhat + co, attn * hv.x, attn * hv.y, attn * hv.z, attn * hv.w);

    float4 wf = *(const float4*)(g_Wfx + co);
    float4 uf = *(const float4*)(g_Ufh + cho);
    float4 cv = *(const float4*)(child_c + cho);
    float fx = sigm_f(wf.x + uf.x) * cv.x;
    float fy = sigm_f(wf.y + uf.y) * cv.y;
    float fz = sigm_f(wf.z + uf.z) * cv.z;
    float fw = sigm_f(wf.w + uf.w) * cv.w;
    red4(g_sumfc + co, fx, fy, fz, fw);
}

// ---------------- epilogue: gates -> h, c ----------------
__global__ void epilogue_kernel(float* __restrict__ outh, float* __restrict__ outc, int n4) {
    int stride = gridDim.x * blockDim.x;
    for (int i = blockIdx.x * blockDim.x + threadIdx.x; i < n4; i += stride) {
        float4 wix = ((const float4*)g_Wix)[i];
        float4 uih = ((const float4*)g_Uih)[i];
        float4 wcx = ((const float4*)g_Wcx)[i];
        float4 uch = ((const float4*)g_Uch)[i];
        float4 wox = ((const float4*)g_Wox)[i];
        float4 uoh = ((const float4*)g_Uoh)[i];
        float4 sf  = ((const float4*)g_sumfc)[i];

        float4 hc, cc;
        {
            float ig = sigm_f(wix.x + uih.x);
            float ct = tanh_f(wcx.x + uch.x);
            float cval = fmaf(ig, ct, sf.x);
            float og = sigm_f(wox.x + uoh.x);
            cc.x = cval; hc.x = og * tanh_f(cval);
        }
        {
            float ig = sigm_f(wix.y + uih.y);
            float ct = tanh_f(wcx.y + uch.y);
            float cval = fmaf(ig, ct, sf.y);
            float og = sigm_f(wox.y + uoh.y);
            cc.y = cval; hc.y = og * tanh_f(cval);
        }
        {
            float ig = sigm_f(wix.z + uih.z);
            float ct = tanh_f(wcx.z + uch.z);
            float cval = fmaf(ig, ct, sf.z);
            float og = sigm_f(wox.z + uoh.z);
            cc.z = cval; hc.z = og * tanh_f(cval);
        }
        {
            float ig = sigm_f(wix.w + uih.w);
            float ct = tanh_f(wcx.w + uch.w);
            float cval = fmaf(ig, ct, sf.w);
            float og = sigm_f(wox.w + uoh.w);
            cc.w = cval; hc.w = og * tanh_f(cval);
        }
        ((float4*)outh)[i] = hc;
        ((float4*)outc)[i] = cc;
    }
}

// ---------------- launch ----------------
extern "C" void kernel_launch(void* const* d_in, const int* in_sizes, int n_in,
                              void* d_out, int out_size) {
    const float* x_emb   = (const float*)d_in[0];
    const float* child_h = (const float*)d_in[1];
    const float* child_c = (const float*)d_in[2];
    const int*   ci      = (const int*)d_in[3];
    const int*   chi     = (const int*)d_in[4];
    const float* Wi_w = (const float*)d_in[5];
    const float* Ui_w = (const float*)d_in[6];
    const float* Wf_w = (const float*)d_in[7];
    const float* Uf_w = (const float*)d_in[8];
    const float* Wo_w = (const float*)d_in[9];
    const float* Uo_w = (const float*)d_in[10];
    const float* Wc_w = (const float*)d_in[11];
    const float* Uc_w = (const float*)d_in[12];
    const float* Wa_w = (const float*)d_in[13];
    const float* Ua_w = (const float*)d_in[14];
    const float* Wi_b = (const float*)d_in[15];
    const float* Wf_b = (const float*)d_in[16];
    const float* Wo_b = (const float*)d_in[17];
    const float* Wc_b = (const float*)d_in[18];
    const float* Wa_b = (const float*)d_in[19];
    const float* v_w  = (const float*)d_in[20];

    const int M = in_sizes[0] / Hd;
    const int L = in_sizes[3];

    float *p_Bx, *p_Wix, *p_Wfx, *p_Wox, *p_Wcx, *p_Ah, *p_Ufh, *p_hhat, *p_Uih, *p_Uch, *p_Uoh;
    cudaGetSymbolAddress((void**)&p_Bx,  g_Bx);
    cudaGetSymbolAddress((void**)&p_Wix, g_Wix);
    cudaGetSymbolAddress((void**)&p_Wfx, g_Wfx);
    cudaGetSymbolAddress((void**)&p_Wox, g_Wox);
    cudaGetSymbolAddress((void**)&p_Wcx, g_Wcx);
    cudaGetSymbolAddress((void**)&p_Ah,  g_Ah);
    cudaGetSymbolAddress((void**)&p_Ufh, g_Ufh);
    cudaGetSymbolAddress((void**)&p_hhat, g_hhat);
    cudaGetSymbolAddress((void**)&p_Uih, g_Uih);
    cudaGetSymbolAddress((void**)&p_Uch, g_Uch);
    cudaGetSymbolAddress((void**)&p_Uoh, g_Uoh);

    float* outh = (float*)d_out;
    float* outc = outh + (size_t)M * Hd;

    const int mtiles = (M + 127) / 128;

    zero_kernel<<<296, 256>>>(M);

    // phase-1 GEMMs (merged x-side + child_h-side, 7 slots, no inter-dependency)
    {
        GemmArgs ga;
        ga.M = M;
        ga.A[0] = x_emb;   ga.W[0] = Ua_w; ga.bias[0] = nullptr; ga.C[0] = p_Bx;
        ga.A[1] = x_emb;   ga.W[1] = Wi_w; ga.bias[1] = Wi_b;    ga.C[1] = p_Wix;
        ga.A[2] = x_emb;   ga.W[2] = Wf_w; ga.bias[2] = Wf_b;    ga.C[2] = p_Wfx;
        ga.A[3] = x_emb;   ga.W[3] = Wo_w; ga.bias[3] = Wo_b;    ga.C[3] = p_Wox;
        ga.A[4] = x_emb;   ga.W[4] = Wc_w; ga.bias[4] = Wc_b;    ga.C[4] = p_Wcx;
        ga.A[5] = child_h; ga.W[5] = Wa_w; ga.bias[5] = Wa_b;    ga.C[5] = p_Ah;
        ga.A[6] = child_h; ga.W[6] = Uf_w; ga.bias[6] = nullptr; ga.C[6] = p_Ufh;
        gemm128<<<dim3(mtiles, 7), 256>>>(ga);
    }

    // attention + forget-gate pair passes
    pair_e_kernel<<<(L + 7) / 8, 256>>>(ci, chi, v_w, L);
    pair_exp_kernel<<<(L + 255) / 256, 256>>>(ci, L);
    pair_acc_kernel<<<(L + 7) / 8, 256>>>(child_h, child_c, ci, chi, L);

    // h_hat-side GEMMs: Uih, Uch, Uoh
    {
        GemmArgs ga;
        ga.M = M;
        ga.A[0] = p_hhat; ga.W[0] = Ui_w; ga.bias[0] = nullptr; ga.C[0] = p_Uih;
        ga.A[1] = p_hhat; ga.W[1] = Uc_w; ga.bias[1] = nullptr; ga.C[1] = p_Uch;
        ga.A[2] = p_hhat; ga.W[2] = Uo_w; ga.bias[2] = nullptr; ga.C[2] = p_Uoh;
        ga.A[3] = p_hhat; ga.W[3] = Ui_w; ga.bias[3] = nullptr; ga.C[3] = p_Uih;  // unused
        ga.A[4] = p_hhat; ga.W[4] = Ui_w; ga.bias[4] = nullptr; ga.C[4] = p_Uih;
        ga.A[5] = p_hhat; ga.W[5] = Ui_w; ga.bias[5] = nullptr; ga.C[5] = p_Uih;
        ga.A[6] = p_hhat; ga.W[6] = Ui_w; ga.bias[6] = nullptr; ga.C[6] = p_Uih;
        gemm128<<<dim3(mtiles, 3), 256>>>(ga);
    }

    const int n4 = M * Hd / 4;
    epilogue_kernel<<<(n4 + 255) / 256, 256>>>(outh, outc, n4);
}

// round 6
// speedup vs baseline: 1.6493x; 1.6010x over previous
#include <cuda_runtime.h>
#include <cuda_bf16.h>
#include <cstdint>

#define Hd 128
#define MAXM 50048
#define MAXL 400128
#define SEPS 1e-9f
#define NT 512

// ---------------- scratch (device globals; no allocations) ----------------
__device__ float g_Bx [MAXM*Hd];
__device__ float g_Wix[MAXM*Hd];
__device__ float g_Wfx[MAXM*Hd];
__device__ float g_Wox[MAXM*Hd];
__device__ float g_Wcx[MAXM*Hd];
__device__ float g_Ah [MAXM*Hd];
__device__ float g_Ufh[MAXM*Hd];
__device__ float g_hhat[MAXM*Hd];
__device__ float g_sumfc[MAXM*Hd];
__device__ float g_Uih[MAXM*Hd];
__device__ float g_Uch[MAXM*Hd];
__device__ float g_Uoh[MAXM*Hd];
__device__ float g_e[MAXL];
__device__ float g_segsum[MAXM];
__device__ unsigned g_segmax[MAXM];
// pre-split, pre-swizzled weights: 10 x 128x128 bf16 (hi & lo), 32KB each
__device__ __align__(16) char g_Wbhi[10 * 32768];
__device__ __align__(16) char g_Wblo[10 * 32768];

// ---------------- scalar helpers ----------------
__device__ __forceinline__ float sigm_f(float x) {
    return __fdividef(1.0f, 1.0f + __expf(-x));
}
__device__ __forceinline__ float tanh_f(float x) {
    float e2 = __expf(2.0f * x);
    return 1.0f - __fdividef(2.0f, e2 + 1.0f);
}
__device__ __forceinline__ unsigned encf(float f) {
    unsigned b = __float_as_uint(f);
    return (b & 0x80000000u) ? ~b : (b | 0x80000000u);
}
__device__ __forceinline__ float decf(unsigned u) {
    return (u & 0x80000000u) ? __uint_as_float(u ^ 0x80000000u) : __uint_as_float(~u);
}
__device__ __forceinline__ void red4(float* p, float x, float y, float z, float w) {
    asm volatile("red.global.add.v4.f32 [%0], {%1, %2, %3, %4};"
                 :: "l"(p), "f"(x), "f"(y), "f"(z), "f"(w) : "memory");
}
__device__ __forceinline__ uint32_t smem_u32(const void* p) {
    uint32_t a;
    asm("{ .reg .u64 t; cvta.to.shared.u64 t, %1; cvt.u32.u64 %0, t; }" : "=r"(a) : "l"(p));
    return a;
}

// ---------------- mma / ldmatrix wrappers (sm_80-class, legal on compute_103) ----
__device__ __forceinline__ void ldm4(uint32_t* r, uint32_t addr) {
    asm volatile("ldmatrix.sync.aligned.m8n8.x4.shared.b16 {%0,%1,%2,%3}, [%4];"
                 : "=r"(r[0]), "=r"(r[1]), "=r"(r[2]), "=r"(r[3]) : "r"(addr));
}
__device__ __forceinline__ void mma16816(float* d, const uint32_t* a, const uint32_t* b) {
    asm volatile("mma.sync.aligned.m16n8k16.row.col.f32.bf16.bf16.f32 "
                 "{%0,%1,%2,%3}, {%4,%5,%6,%7}, {%8,%9}, {%0,%1,%2,%3};"
                 : "+f"(d[0]), "+f"(d[1]), "+f"(d[2]), "+f"(d[3])
                 : "r"(a[0]), "r"(a[1]), "r"(a[2]), "r"(a[3]), "r"(b[0]), "r"(b[1]));
}

// swizzled byte offset of (row, colbyte) in a 128-row x 256B tile
__device__ __forceinline__ uint32_t swz(int row, int colbyte) {
    return (uint32_t)(row * 256 + (colbyte ^ ((row & 7) << 4)));
}
// pack two f32 into bf16 hi pair and residual lo pair
__device__ __forceinline__ void split2(float x, float y, uint32_t& hp, uint32_t& lp) {
    __nv_bfloat16 hx = __float2bfloat16(x);
    __nv_bfloat16 hy = __float2bfloat16(y);
    __nv_bfloat16 lx = __float2bfloat16(x - __bfloat162float(hx));
    __nv_bfloat16 ly = __float2bfloat16(y - __bfloat162float(hy));
    hp = ((uint32_t)__bfloat16_as_ushort(hy) << 16) | __bfloat16_as_ushort(hx);
    lp = ((uint32_t)__bfloat16_as_ushort(ly) << 16) | __bfloat16_as_ushort(lx);
}

// ---------------- prep: zero accumulators + pre-split all 10 weights ----------------
struct PrepArgs { const float* W[10]; };

__global__ void prep_kernel(PrepArgs pa, int M) {
    int stride = gridDim.x * blockDim.x;
    int gt = blockIdx.x * blockDim.x + threadIdx.x;
    int n4 = M * Hd / 4;
    float4 z = make_float4(0.f, 0.f, 0.f, 0.f);
    for (int i = gt; i < n4; i += stride) {
        ((float4*)g_hhat)[i]  = z;
        ((float4*)g_sumfc)[i] = z;
    }
    for (int i = gt; i < M; i += stride) {
        g_segsum[i] = 0.f;
        g_segmax[i] = 0u;
    }
    // split weights: 10 x 128 rows x 64 float2
    for (int idx = gt; idx < 10 * 8192; idx += stride) {
        int w = idx >> 13;
        int i = idx & 8191;
        int row = i >> 6;
        int c2 = i & 63;                       // float2 index within row
        float2 v = *(const float2*)(pa.W[w] + (size_t)row * Hd + c2 * 2);
        uint32_t hp, lp;
        split2(v.x, v.y, hp, lp);
        uint32_t off = swz(row, c2 * 4);
        *(uint32_t*)(g_Wbhi + w * 32768 + off) = hp;
        *(uint32_t*)(g_Wblo + w * 32768 + off) = lp;
    }
}

// ---------------- tensor-core batched GEMM: C = A @ W^T (+bias), bf16x3 ----------------
struct TcArgs {
    const float* A1;
    const float* A2;
    const char* whi[7];
    const char* wlo[7];
    const float* b[7];
    float* C[7];
    int nW1, nW2, M;
};

#define SA_HI 0
#define SA_LO 32768
#define SW_HI 65536
#define SW_LO 98304
#define S_BIAS 131072
#define S_TOT  (131072 + 512)

__device__ __forceinline__ void conv_tile(const float* __restrict__ A, int m0, int M,
                                          char* hi, char* lo, int tid) {
#pragma unroll
    for (int it = 0; it < 8192 / NT; it++) {
        int i = tid + it * NT;
        int row = i >> 6;
        int c2 = i & 63;
        float2 v = make_float2(0.f, 0.f);
        if (m0 + row < M) v = *(const float2*)(A + (size_t)(m0 + row) * Hd + c2 * 2);
        uint32_t hp, lp;
        split2(v.x, v.y, hp, lp);
        uint32_t off = swz(row, c2 * 4);
        *(uint32_t*)(hi + off) = hp;
        *(uint32_t*)(lo + off) = lp;
    }
}

__global__ void __launch_bounds__(NT, 1) gemm_mma(TcArgs ga) {
    extern __shared__ char sm[];
    const uint32_t smb = smem_u32(sm);
    const int tid = threadIdx.x;
    const int wid = tid >> 5;
    const int lane = tid & 31;
    const int m0 = blockIdx.x * 128;
    const int M = ga.M;
    const int wm = wid >> 2;          // 0..3 -> 32-row slice
    const int wn = wid & 3;           // 0..3 -> 32-col slice

    const int sub = lane & 7;
    const int quad = lane >> 3;
    // ldmatrix lane->address components
    const int arow0 = wm * 32 + sub + (quad & 1) * 8;   // + ti*16
    const int akb   = (quad >> 1) * 16;
    const int brow0 = wn * 32 + sub + (quad >> 1) * 8;  // + tp*16
    const int bkb   = (quad & 1) * 16;

    const float* Acur = ga.A1;
    int nW = ga.nW1;
    int wbase = 0;

    for (int sec = 0; sec < 2; sec++) {
        if (nW == 0) break;
        __syncthreads();                 // prior section's reads of A smem done
        conv_tile(Acur, m0, M, sm + SA_HI, sm + SA_LO, tid);

        for (int wi = 0; wi < nW; wi++) {
            const int w = wbase + wi;
            __syncthreads();             // prior weight's reads of W smem done
            // fill W smem (pre-swizzled: straight copy)
            {
                const uint4* shi = (const uint4*)ga.whi[w];
                const uint4* slo = (const uint4*)ga.wlo[w];
#pragma unroll
                for (int it = 0; it < 2048 / NT; it++) {
                    int i = tid + it * NT;
                    ((uint4*)(sm + SW_HI))[i] = shi[i];
                    ((uint4*)(sm + SW_LO))[i] = slo[i];
                }
            }
            if (tid < 128) ((float*)(sm + S_BIAS))[tid] = ga.b[w] ? __ldg(ga.b[w] + tid) : 0.f;
            __syncthreads();

            float acc[2][4][4];
#pragma unroll
            for (int ti = 0; ti < 2; ti++)
#pragma unroll
                for (int tj = 0; tj < 4; tj++)
#pragma unroll
                    for (int k = 0; k < 4; k++) acc[ti][tj][k] = 0.f;

#pragma unroll
            for (int ks = 0; ks < 8; ks++) {
                const int kb0 = ks * 32;
                uint32_t ah[2][4], al[2][4], bh[2][4], bl[2][4];
#pragma unroll
                for (int ti = 0; ti < 2; ti++) {
                    int row = arow0 + ti * 16;
                    uint32_t off = swz(row, kb0 + akb);
                    ldm4(ah[ti], smb + SA_HI + off);
                    ldm4(al[ti], smb + SA_LO + off);
                }
#pragma unroll
                for (int tp = 0; tp < 2; tp++) {
                    int row = brow0 + tp * 16;
                    uint32_t off = swz(row, kb0 + bkb);
                    ldm4(bh[tp], smb + SW_HI + off);
                    ldm4(bl[tp], smb + SW_LO + off);
                }
#pragma unroll
                for (int ti = 0; ti < 2; ti++)
#pragma unroll
                    for (int tj = 0; tj < 4; tj++) {
                        const uint32_t* bhp = &bh[tj >> 1][(tj & 1) * 2];
                        const uint32_t* blp = &bl[tj >> 1][(tj & 1) * 2];
                        mma16816(acc[ti][tj], ah[ti], bhp);   // hi*hi
                        mma16816(acc[ti][tj], ah[ti], blp);   // hi*lo
                        mma16816(acc[ti][tj], al[ti], bhp);   // lo*hi
                    }
            }

            // store C tile (+bias)
            {
                const int g = lane >> 2;
                const int tg = lane & 3;
                float* __restrict__ C = ga.C[w];
                const float* sb = (const float*)(sm + S_BIAS);
#pragma unroll
                for (int ti = 0; ti < 2; ti++)
#pragma unroll
                    for (int tj = 0; tj < 4; tj++) {
                        int row = m0 + wm * 32 + ti * 16 + g;
                        int col = wn * 32 + tj * 8 + tg * 2;
                        float2 bv = *(const float2*)(sb + col);
                        if (row < M) {
                            float2 o = make_float2(acc[ti][tj][0] + bv.x,
                                                   acc[ti][tj][1] + bv.y);
                            *(float2*)(C + (size_t)row * Hd + col) = o;
                        }
                        if (row + 8 < M) {
                            float2 o = make_float2(acc[ti][tj][2] + bv.x,
                                                   acc[ti][tj][3] + bv.y);
                            *(float2*)(C + (size_t)(row + 8) * Hd + col) = o;
                        }
                    }
            }
        }
        wbase += nW;
        Acur = ga.A2;
        nW = ga.nW2;
    }
}

// ---------------- pair pass 1 ----------------
__global__ void pair_e_kernel(const int* __restrict__ ci, const int* __restrict__ chi,
                              const float* __restrict__ v, int L) {
    __shared__ float vs[Hd];
    if (threadIdx.x < Hd) vs[threadIdx.x] = v[threadIdx.x];
    __syncthreads();

    int w = blockIdx.x * (blockDim.x >> 5) + (threadIdx.x >> 5);
    int lane = threadIdx.x & 31;
    if (w >= L) return;

    int c  = __ldg(ci + w);
    int ch = __ldg(chi + w);
    float4 a  = *(const float4*)(g_Ah + (size_t)ch * Hd + lane * 4);
    float4 b  = *(const float4*)(g_Bx + (size_t)c * Hd + lane * 4);
    float4 vv = *(const float4*)(vs + lane * 4);

    float s = tanh_f(a.x + b.x) * vv.x + tanh_f(a.y + b.y) * vv.y +
              tanh_f(a.z + b.z) * vv.z + tanh_f(a.w + b.w) * vv.w;
#pragma unroll
    for (int o = 16; o; o >>= 1) s += __shfl_xor_sync(0xFFFFFFFFu, s, o);

    if (lane == 0) {
        g_e[w] = s;
        atomicMax(g_segmax + c, encf(s));
    }
}

// ---------------- pair pass 2 ----------------
__global__ void pair_exp_kernel(const int* __restrict__ ci, int L) {
    int l = blockIdx.x * blockDim.x + threadIdx.x;
    if (l >= L) return;
    int c = ci[l];
    float mx = decf(g_segmax[c]);
    float xe = __expf(g_e[l] - mx);
    g_e[l] = xe;
    atomicAdd(g_segsum + c, xe);
}

// ---------------- pair pass 3 ----------------
__global__ void pair_acc_kernel(const float* __restrict__ child_h,
                                const float* __restrict__ child_c,
                                const int* __restrict__ ci, const int* __restrict__ chi,
                                int L) {
    int w = blockIdx.x * (blockDim.x >> 5) + (threadIdx.x >> 5);
    int lane = threadIdx.x & 31;
    if (w >= L) return;

    int c  = __ldg(ci + w);
    int ch = __ldg(chi + w);
    float attn = __ldg(g_e + w) / (__ldg(g_segsum + c) + SEPS);

    size_t co  = (size_t)c * Hd + lane * 4;
    size_t cho = (size_t)ch * Hd + lane * 4;

    float4 hv = *(const float4*)(child_h + cho);
    red4(g_hhat + co, attn * hv.x, attn * hv.y, attn * hv.z, attn * hv.w);

    float4 wf = *(const float4*)(g_Wfx + co);
    float4 uf = *(const float4*)(g_Ufh + cho);
    float4 cv = *(const float4*)(child_c + cho);
    float fx = sigm_f(wf.x + uf.x) * cv.x;
    float fy = sigm_f(wf.y + uf.y) * cv.y;
    float fz = sigm_f(wf.z + uf.z) * cv.z;
    float fw = sigm_f(wf.w + uf.w) * cv.w;
    red4(g_sumfc + co, fx, fy, fz, fw);
}

// ---------------- epilogue ----------------
__global__ void epilogue_kernel(float* __restrict__ outh, float* __restrict__ outc, int n4) {
    int stride = gridDim.x * blockDim.x;
    for (int i = blockIdx.x * blockDim.x + threadIdx.x; i < n4; i += stride) {
        float4 wix = ((const float4*)g_Wix)[i];
        float4 uih = ((const float4*)g_Uih)[i];
        float4 wcx = ((const float4*)g_Wcx)[i];
        float4 uch = ((const float4*)g_Uch)[i];
        float4 wox = ((const float4*)g_Wox)[i];
        float4 uoh = ((const float4*)g_Uoh)[i];
        float4 sf  = ((const float4*)g_sumfc)[i];

        float4 hc, cc;
        {
            float ig = sigm_f(wix.x + uih.x);
            float ct = tanh_f(wcx.x + uch.x);
            float cval = fmaf(ig, ct, sf.x);
            float og = sigm_f(wox.x + uoh.x);
            cc.x = cval; hc.x = og * tanh_f(cval);
        }
        {
            float ig = sigm_f(wix.y + uih.y);
            float ct = tanh_f(wcx.y + uch.y);
            float cval = fmaf(ig, ct, sf.y);
            float og = sigm_f(wox.y + uoh.y);
            cc.y = cval; hc.y = og * tanh_f(cval);
        }
        {
            float ig = sigm_f(wix.z + uih.z);
            float ct = tanh_f(wcx.z + uch.z);
            float cval = fmaf(ig, ct, sf.z);
            float og = sigm_f(wox.z + uoh.z);
            cc.z = cval; hc.z = og * tanh_f(cval);
        }
        {
            float ig = sigm_f(wix.w + uih.w);
            float ct = tanh_f(wcx.w + uch.w);
            float cval = fmaf(ig, ct, sf.w);
            float og = sigm_f(wox.w + uoh.w);
            cc.w = cval; hc.w = og * tanh_f(cval);
        }
        ((float4*)outh)[i] = hc;
        ((float4*)outc)[i] = cc;
    }
}

// ---------------- launch ----------------
extern "C" void kernel_launch(void* const* d_in, const int* in_sizes, int n_in,
                              void* d_out, int out_size) {
    const float* x_emb   = (const float*)d_in[0];
    const float* child_h = (const float*)d_in[1];
    const float* child_c = (const float*)d_in[2];
    const int*   ci      = (const int*)d_in[3];
    const int*   chi     = (const int*)d_in[4];
    const float* Wi_w = (const float*)d_in[5];
    const float* Ui_w = (const float*)d_in[6];
    const float* Wf_w = (const float*)d_in[7];
    const float* Uf_w = (const float*)d_in[8];
    const float* Wo_w = (const float*)d_in[9];
    const float* Uo_w = (const float*)d_in[10];
    const float* Wc_w = (const float*)d_in[11];
    const float* Uc_w = (const float*)d_in[12];
    const float* Wa_w = (const float*)d_in[13];
    const float* Ua_w = (const float*)d_in[14];
    const float* Wi_b = (const float*)d_in[15];
    const float* Wf_b = (const float*)d_in[16];
    const float* Wo_b = (const float*)d_in[17];
    const float* Wc_b = (const float*)d_in[18];
    const float* Wa_b = (const float*)d_in[19];
    const float* v_w  = (const float*)d_in[20];

    const int M = in_sizes[0] / Hd;
    const int L = in_sizes[3];

    float *p_Bx, *p_Wix, *p_Wfx, *p_Wox, *p_Wcx, *p_Ah, *p_Ufh, *p_hhat, *p_Uih, *p_Uch, *p_Uoh;
    cudaGetSymbolAddress((void**)&p_Bx,  g_Bx);
    cudaGetSymbolAddress((void**)&p_Wix, g_Wix);
    cudaGetSymbolAddress((void**)&p_Wfx, g_Wfx);
    cudaGetSymbolAddress((void**)&p_Wox, g_Wox);
    cudaGetSymbolAddress((void**)&p_Wcx, g_Wcx);
    cudaGetSymbolAddress((void**)&p_Ah,  g_Ah);
    cudaGetSymbolAddress((void**)&p_Ufh, g_Ufh);
    cudaGetSymbolAddress((void**)&p_hhat, g_hhat);
    cudaGetSymbolAddress((void**)&p_Uih, g_Uih);
    cudaGetSymbolAddress((void**)&p_Uch, g_Uch);
    cudaGetSymbolAddress((void**)&p_Uoh, g_Uoh);
    char *p_whi, *p_wlo;
    cudaGetSymbolAddress((void**)&p_whi, g_Wbhi);
    cudaGetSymbolAddress((void**)&p_wlo, g_Wblo);

    float* outh = (float*)d_out;
    float* outc = outh + (size_t)M * Hd;

    const int mtiles = (M + 127) / 128;

    cudaFuncSetAttribute(gemm_mma, cudaFuncAttributeMaxDynamicSharedMemorySize, S_TOT);

    // weight order in g_Wb: 0:Ua 1:Wi 2:Wf 3:Wo 4:Wc 5:Wa 6:Uf 7:Ui 8:Uc 9:Uo
    {
        PrepArgs pa;
        pa.W[0] = Ua_w; pa.W[1] = Wi_w; pa.W[2] = Wf_w; pa.W[3] = Wo_w; pa.W[4] = Wc_w;
        pa.W[5] = Wa_w; pa.W[6] = Uf_w; pa.W[7] = Ui_w; pa.W[8] = Uc_w; pa.W[9] = Uo_w;
        prep_kernel<<<296, 256>>>(pa, M);
    }

    // phase 1: x-side (Bx, Wix, Wfx, Wox, Wcx) + child_h-side (Ah, Ufh)
    {
        TcArgs ga;
        ga.A1 = x_emb; ga.A2 = child_h; ga.nW1 = 5; ga.nW2 = 2; ga.M = M;
        int slot[7] = {0, 1, 2, 3, 4, 5, 6};
        const float* bs[7] = {nullptr, Wi_b, Wf_b, Wo_b, Wc_b, Wa_b, nullptr};
        float* cs[7] = {p_Bx, p_Wix, p_Wfx, p_Wox, p_Wcx, p_Ah, p_Ufh};
        for (int i = 0; i < 7; i++) {
            ga.whi[i] = p_whi + slot[i] * 32768;
            ga.wlo[i] = p_wlo + slot[i] * 32768;
            ga.b[i] = bs[i];
            ga.C[i] = cs[i];
        }
        gemm_mma<<<mtiles, NT, S_TOT>>>(ga);
    }

    // attention + forget-gate pair passes
    pair_e_kernel<<<(L + 7) / 8, 256>>>(ci, chi, v_w, L);
    pair_exp_kernel<<<(L + 255) / 256, 256>>>(ci, L);
    pair_acc_kernel<<<(L + 7) / 8, 256>>>(child_h, child_c, ci, chi, L);

    // phase 3: h_hat-side (Uih, Uch, Uoh)
    {
        TcArgs ga;
        ga.A1 = p_hhat; ga.A2 = nullptr; ga.nW1 = 3; ga.nW2 = 0; ga.M = M;
        int slot[7] = {7, 8, 9, 7, 7, 7, 7};
        float* cs[7] = {p_Uih, p_Uch, p_Uoh, p_Uih, p_Uih, p_Uih, p_Uih};
        for (int i = 0; i < 7; i++) {
            ga.whi[i] = p_whi + slot[i] * 32768;
            ga.wlo[i] = p_wlo + slot[i] * 32768;
            ga.b[i] = nullptr;
            ga.C[i] = cs[i];
        }
        gemm_mma<<<mtiles, NT, S_TOT>>>(ga);
    }

    const int n4 = M * Hd / 4;
    epilogue_kernel<<<(n4 + 255) / 256, 256>>>(outh, outc, n4);
}